// round 1
// baseline (speedup 1.0000x reference)
#include <cuda_runtime.h>
#include <cstdint>
#include <cstddef>

// ---------------------------------------------------------------------------
// Quantizer: VQ nearest-neighbor + straight-through + MSE
//   grid_feat: [8, 256, 16, 16, 16] fp32   (b, c, spatial)
//   weight:    [4096, 256] fp32            (codebook)
// Outputs (concatenated fp32):
//   quant_feat [8,256,4096] | quant_feat_st [same] | enc_idx [32768] | quant_diff [1]
// ---------------------------------------------------------------------------

namespace {
constexpr int KDIM    = 256;
constexpr int VCODES  = 4096;
constexpr int SPATIAL = 4096;           // 16*16*16
constexpr int BATCH   = 8;
constexpr int NROWS   = BATCH * SPATIAL;                 // 32768
constexpr long long NQ = (long long)BATCH * KDIM * SPATIAL; // 8388608

constexpr int BN = 128;   // rows per block
constexpr int BV = 128;   // codes per v-tile
constexpr int KC = 32;    // k-chunk
constexpr int NBLOCKS = NROWS / BN;     // 256

constexpr int SMEM_BYTES =
    (KDIM * BN            // Fs  [256][128] fp32  = 128 KB
     + 2 * KC * BN) * 4   // Wsm [2][32][128] fp32 = 32 KB
    + BN * 4              // rowidx_s
    + 256 * 4;            // red
}

// Scratch (device globals; no allocation allowed in kernel_launch)
__device__ float g_Wt[KDIM * VCODES];   // W transposed: [c][v]
__device__ float g_wnorm[VCODES];       // ||w_v||^2
__device__ float g_partial[NBLOCKS];    // per-block sum of (g - q)^2

// ---------------------------------------------------------------------------
// Prep 1: transpose weight [4096,256] -> g_Wt [256,4096]
// ---------------------------------------------------------------------------
__global__ void vq_transpose_kernel(const float* __restrict__ W) {
    __shared__ float tile[32][33];
    const int v0 = blockIdx.x * 32;   // code dim
    const int c0 = blockIdx.y * 32;   // channel dim
    const int tx = threadIdx.x;       // 0..31
    const int ty = threadIdx.y;       // 0..7
    #pragma unroll
    for (int j = 0; j < 32; j += 8)
        tile[ty + j][tx] = W[(size_t)(v0 + ty + j) * KDIM + c0 + tx];
    __syncthreads();
    #pragma unroll
    for (int j = 0; j < 32; j += 8)
        g_Wt[(size_t)(c0 + ty + j) * VCODES + v0 + tx] = tile[tx][ty + j];
}

// ---------------------------------------------------------------------------
// Prep 2: ||w_v||^2 (one warp per code)
// ---------------------------------------------------------------------------
__global__ void vq_wnorm_kernel(const float* __restrict__ W) {
    const int v    = blockIdx.x * 8 + (threadIdx.x >> 5);
    const int lane = threadIdx.x & 31;
    const float4* p = reinterpret_cast<const float4*>(W + (size_t)v * KDIM);
    float s = 0.f;
    #pragma unroll
    for (int i = 0; i < 2; i++) {
        float4 x = p[lane * 2 + i];
        s += x.x * x.x + x.y * x.y + x.z * x.z + x.w * x.w;
    }
    #pragma unroll
    for (int o = 16; o > 0; o >>= 1) s += __shfl_xor_sync(0xffffffffu, s, o);
    if (lane == 0) g_wnorm[v] = s;
}

// ---------------------------------------------------------------------------
// Main: fused distance GEMM + argmin + gather + straight-through + MSE partial
// 256 blocks x 256 threads. Block = 128 rows; loops over 32 v-tiles of 128.
// Thread (tx,ty) in 16x16 grid owns 8x8 micro-tile:
//   rows:  4*ty+{0..3}, 64+4*ty+{0..3}
//   cols:  4*tx+{0..3}, 64+4*tx+{0..3}
// ---------------------------------------------------------------------------
__global__ void __launch_bounds__(256, 1)
vq_main_kernel(const float* __restrict__ grid_feat, float* __restrict__ out) {
    extern __shared__ float smem[];
    float* Fs  = smem;                  // [KDIM][BN], k-major
    float* Wsm = Fs + KDIM * BN;        // [2][KC][BN], k-major
    int*   rowidx_s = (int*)(Wsm + 2 * KC * BN);
    float* red = (float*)(rowidx_s + BN);

    const int t  = threadIdx.x;
    const int tx = t & 15;
    const int ty = t >> 4;
    const int n0 = blockIdx.x * BN;
    const int b  = n0 >> 12;                 // n0 / SPATIAL
    const int p0 = n0 & (SPATIAL - 1);
    const float* gbase = grid_feat + (size_t)b * KDIM * SPATIAL + p0;

    // ---- Load F tile: gmem [c][p] is already k-major; coalesced float4 along p
    {
        const int cq = t >> 5;               // 0..7
        const int r4 = (t & 31) << 2;        // 0..124
        #pragma unroll
        for (int i = 0; i < KDIM / 8; i++) {
            const int c = i * 8 + cq;
            float4 v = *reinterpret_cast<const float4*>(gbase + (size_t)c * SPATIAL + r4);
            *reinterpret_cast<float4*>(Fs + c * BN + r4) = v;
        }
    }
    __syncthreads();

    float rmin[8];
    int   ridx[8];
    #pragma unroll
    for (int i = 0; i < 8; i++) { rmin[i] = 3.4e38f; ridx[i] = 0; }

    const int wkq = t >> 5;            // kk sub-row for W chunk loads
    const int wv4 = (t & 31) << 2;     // v offset (float4)

    for (int vt = 0; vt < VCODES / BV; vt++) {
        const int vb = vt * BV;
        float acc[8][8];
        #pragma unroll
        for (int i = 0; i < 8; i++)
            #pragma unroll
            for (int j = 0; j < 8; j++) acc[i][j] = 0.f;

        // Preload chunk 0 (Wt rows: v contiguous -> coalesced; smem conflict-free)
        float4 stg[4];
        #pragma unroll
        for (int p = 0; p < 4; p++)
            stg[p] = *reinterpret_cast<const float4*>(
                g_Wt + (size_t)(p * 8 + wkq) * VCODES + vb + wv4);
        #pragma unroll
        for (int p = 0; p < 4; p++)
            *reinterpret_cast<float4*>(Wsm + (p * 8 + wkq) * BN + wv4) = stg[p];
        __syncthreads();

        #pragma unroll 1
        for (int kc = 0; kc < KDIM / KC; kc++) {
            const int cur = kc & 1;
            const bool has_next = (kc + 1 < KDIM / KC);
            if (has_next) {
                const int kb = (kc + 1) * KC;
                #pragma unroll
                for (int p = 0; p < 4; p++)
                    stg[p] = *reinterpret_cast<const float4*>(
                        g_Wt + (size_t)(kb + p * 8 + wkq) * VCODES + vb + wv4);
            }
            const float* fbase = Fs + kc * KC * BN;
            const float* wbase = Wsm + cur * KC * BN;
            #pragma unroll 8
            for (int kk = 0; kk < KC; kk++) {
                float4 a0 = *reinterpret_cast<const float4*>(fbase + kk * BN + 4 * ty);
                float4 a1 = *reinterpret_cast<const float4*>(fbase + kk * BN + 64 + 4 * ty);
                float4 b0 = *reinterpret_cast<const float4*>(wbase + kk * BN + 4 * tx);
                float4 b1 = *reinterpret_cast<const float4*>(wbase + kk * BN + 64 + 4 * tx);
                const float av[8] = {a0.x, a0.y, a0.z, a0.w, a1.x, a1.y, a1.z, a1.w};
                const float bv[8] = {b0.x, b0.y, b0.z, b0.w, b1.x, b1.y, b1.z, b1.w};
                #pragma unroll
                for (int i = 0; i < 8; i++)
                    #pragma unroll
                    for (int j = 0; j < 8; j++)
                        acc[i][j] = fmaf(av[i], bv[j], acc[i][j]);
            }
            if (has_next) {
                const int nb = cur ^ 1;
                #pragma unroll
                for (int p = 0; p < 4; p++)
                    *reinterpret_cast<float4*>(Wsm + nb * KC * BN + (p * 8 + wkq) * BN + wv4) = stg[p];
                __syncthreads();
            }
        }

        // Epilogue: d = ||w||^2 - 2*f.w   (row-constant ||f||^2 dropped; argmin invariant)
        float wn[8];
        #pragma unroll
        for (int j = 0; j < 8; j++) {
            const int v = vb + ((j < 4) ? 4 * tx + j : 64 + 4 * tx + (j - 4));
            wn[j] = __ldg(&g_wnorm[v]);
        }
        #pragma unroll
        for (int i = 0; i < 8; i++)
            #pragma unroll
            for (int j = 0; j < 8; j++) {
                const int v = vb + ((j < 4) ? 4 * tx + j : 64 + 4 * tx + (j - 4));
                const float d = wn[j] - 2.f * acc[i][j];
                if (d < rmin[i]) { rmin[i] = d; ridx[i] = v; }   // v ascending -> first-min tie-break
            }
    }

    // Cross-tx reduction (16 lanes per group; lane = (ty&1)*16 + tx)
    #pragma unroll
    for (int i = 0; i < 8; i++) {
        float v = rmin[i];
        int  id = ridx[i];
        #pragma unroll
        for (int o = 8; o > 0; o >>= 1) {
            const float ov = __shfl_xor_sync(0xffffffffu, v, o);
            const int  oid = __shfl_xor_sync(0xffffffffu, id, o);
            if (ov < v || (ov == v && oid < id)) { v = ov; id = oid; }
        }
        if (tx == 0) {
            const int row = (i < 4) ? 4 * ty + i : 64 + 4 * ty + (i - 4);
            rowidx_s[row] = id;
        }
    }
    __syncthreads();

    // ---- Output phase: coalesced along spatial; g from resident Fs (exact ST)
    float diffsum = 0.f;
    const size_t obase = (size_t)b * KDIM * SPATIAL + p0;
    #pragma unroll 4
    for (int i = 0; i < 128; i++) {
        const int c   = 2 * i + (t >> 7);
        const int row = t & 127;
        const int vi  = rowidx_s[row];
        const float q = g_Wt[(size_t)c * VCODES + vi];
        const float g = Fs[c * BN + row];
        const float st = (q - g) + g;       // exact replica of stop-gradient forward
        const float dd = g - q;
        diffsum += dd * dd;
        const size_t o = obase + (size_t)c * SPATIAL + row;
        out[o]      = q;                    // quant_feat
        out[NQ + o] = st;                   // quant_feat_st
    }
    if (t < BN) out[2 * NQ + n0 + t] = (float)rowidx_s[t];   // enc_idx

    red[t] = diffsum;
    __syncthreads();
    #pragma unroll
    for (int o = 128; o > 0; o >>= 1) {
        if (t < o) red[t] += red[t + o];
        __syncthreads();
    }
    if (t == 0) g_partial[blockIdx.x] = red[0];
}

// ---------------------------------------------------------------------------
// Final: sum 256 partials -> quant_diff (deterministic, no atomics)
// ---------------------------------------------------------------------------
__global__ void vq_final_kernel(float* __restrict__ out) {
    __shared__ float red[NBLOCKS];
    const int t = threadIdx.x;
    red[t] = g_partial[t];
    __syncthreads();
    #pragma unroll
    for (int o = 128; o > 0; o >>= 1) {
        if (t < o) red[t] += red[t + o];
        __syncthreads();
    }
    if (t == 0) out[2 * NQ + NROWS] = red[0] * (1.f / (float)NQ);
}

// ---------------------------------------------------------------------------
extern "C" void kernel_launch(void* const* d_in, const int* in_sizes, int n_in,
                              void* d_out, int out_size) {
    const float* grid_feat = (const float*)d_in[0];
    const float* weight    = (const float*)d_in[1];
    float* out = (float*)d_out;

    cudaFuncSetAttribute(vq_main_kernel,
                         cudaFuncAttributeMaxDynamicSharedMemorySize, SMEM_BYTES);

    vq_transpose_kernel<<<dim3(VCODES / 32, KDIM / 32), dim3(32, 8)>>>(weight);
    vq_wnorm_kernel<<<VCODES / 8, 256>>>(weight);
    vq_main_kernel<<<NBLOCKS, 256, SMEM_BYTES>>>(grid_feat, out);
    vq_final_kernel<<<1, NBLOCKS>>>(out);
}

// round 3
// speedup vs baseline: 1.4339x; 1.4339x over previous
#include <cuda_runtime.h>
#include <cuda_fp16.h>
#include <cstdint>
#include <cstddef>

// ============================================================================
// VQ quantizer via legacy mma.sync m16n8k16 fp16, 4-pass hi/lo split (fp32-grade)
//   scores = F.W^T (argmin of ||w||^2 - 2*scores), K_eff = 4*256
//   grid_feat [8,256,16,16,16] f32 ; weight [4096,256] f32
// out: quant_feat[8.4M] | quant_feat_st[8.4M] | enc_idx[32768] | quant_diff[1]
// ============================================================================

namespace {
constexpr int KDIM    = 256;
constexpr int VCODES  = 4096;
constexpr int SPATIAL = 4096;
constexpr int NROWS   = 32768;
constexpr long long NQ = 8388608LL;

constexpr int MT  = 128;            // rows per CTA
constexpr int NTT = 256;            // codes per v-tile
constexpr int NRT = NROWS / MT;     // 256 row-tile CTAs
constexpr int NVT = VCODES / NTT;   // 16 v-tiles

// A image per rt: [2 blk(hi,lo)][16 kt][8 mt][32 lane][4 u32]  = 32768 u32 (128KB)
constexpr int A_RT_U32  = 32768;
constexpr int A_BLK_F4  = 4096;     // f4 per blk
constexpr int A_KT_F4   = 256;      // f4 per kt
// B image per vt: [2 blk][16 kt][16 ntp][32 lane][4 u32]       = 65536 u32 (256KB)
constexpr int B_VT_F4   = 16384;
constexpr int B_BLK_F4  = 8192;
constexpr int B_KT_F4   = 512;

// chunk = 32 k elements = 2 kt ; per vt: 4 passes x 8 chunks = 32
constexpr int CH_PER_VT = 32;
constexpr int TOTAL_CH  = NVT * CH_PER_VT;      // 512
constexpr int A_CH_F4   = 2 * A_KT_F4;          // 512 f4 (8KB)
constexpr int B_CH_F4   = 2 * B_KT_F4;          // 1024 f4 (16KB)
constexpr int STAGE_F4  = A_CH_F4 + B_CH_F4;    // 1536 f4 (24KB)
constexpr int NSTAGES   = 3;
constexpr int SMEM_MAIN = NSTAGES * STAGE_F4 * 16;   // 73728 B
}

// --------------------------- device scratch --------------------------------
__device__ uint32_t g_Aimg[(size_t)NRT * A_RT_U32];   // 32 MB
__device__ uint32_t g_Bimg[(size_t)NVT * 4 * B_VT_F4];// 4 MB (u32 = 4*f4count)
__device__ float    g_Wt[KDIM * VCODES];              // W^T for gather
__device__ float    g_wnorm[VCODES];
__device__ float    g_partial[NRT];

// --------------------------- helpers ---------------------------------------
__device__ __forceinline__ uint32_t smem_u32(const void* p) {
    uint32_t a;
    asm("{ .reg .u64 t; cvta.to.shared.u64 t, %1; cvt.u32.u64 %0, t; }"
        : "=r"(a) : "l"(p));
    return a;
}
__device__ __forceinline__ void cp16(uint32_t s, const void* g) {
    asm volatile("cp.async.cg.shared.global [%0], [%1], 16;" :: "r"(s), "l"(g));
}
#define CP_COMMIT()  asm volatile("cp.async.commit_group;" ::: "memory")
#define CP_WAIT(N)   asm volatile("cp.async.wait_group %0;" :: "n"(N) : "memory")

__device__ __forceinline__ void mma16816(float* c, const uint4& a,
                                         uint32_t b0, uint32_t b1) {
    asm volatile(
        "mma.sync.aligned.m16n8k16.row.col.f32.f16.f16.f32 "
        "{%0,%1,%2,%3}, {%4,%5,%6,%7}, {%8,%9}, {%0,%1,%2,%3};"
        : "+f"(c[0]), "+f"(c[1]), "+f"(c[2]), "+f"(c[3])
        : "r"(a.x), "r"(a.y), "r"(a.z), "r"(a.w), "r"(b0), "r"(b1));
}

__device__ __forceinline__ void split2(float v0, float v1,
                                       uint32_t& hi, uint32_t& lo) {
    __half h0 = __float2half_rn(v0), h1 = __float2half_rn(v1);
    __half l0 = __float2half_rn(v0 - __half2float(h0));
    __half l1 = __float2half_rn(v1 - __half2float(h1));
    hi = (uint32_t)__half_as_ushort(h0) | ((uint32_t)__half_as_ushort(h1) << 16);
    lo = (uint32_t)__half_as_ushort(l0) | ((uint32_t)__half_as_ushort(l1) << 16);
}

// ============================================================================
// Prep A: grid_feat -> fragment-major hi/lo fp16 images
// block = (rt 256, cg 8); cg covers channels [cg*32, cg*32+32) = kt {2cg, 2cg+1}
// ============================================================================
__global__ void vq_prepA(const float* __restrict__ gf) {
    __shared__ float sr[32 * 129];
    const int rt = blockIdx.x, cg = blockIdx.y, t = threadIdx.x;
    const int n0 = rt * MT, b = n0 >> 12, p0 = n0 & (SPATIAL - 1);
    const float* base = gf + (size_t)b * KDIM * SPATIAL + (size_t)(cg * 32) * SPATIAL + p0;

    for (int i = t; i < 32 * 128; i += 256) {
        const int c = i >> 7, r = i & 127;            // coalesced along spatial
        sr[c * 129 + r] = base[(size_t)c * SPATIAL + r];
    }
    __syncthreads();

    uint4* ob = (uint4*)(g_Aimg + (size_t)rt * A_RT_U32);
    #pragma unroll
    for (int q = 0; q < 2; q++) {
        const int tup = q * 256 + t;                  // 512 tuples
        const int ktl = tup >> 8, mt = (tup >> 5) & 7, l = tup & 31;
        const int m0 = mt * 16 + (l >> 2);
        const int k0 = ktl * 16 + (l & 3) * 2;
        uint32_t hi[4], lo[4];
        split2(sr[k0 * 129 + m0],           sr[(k0 + 1) * 129 + m0],           hi[0], lo[0]);
        split2(sr[k0 * 129 + m0 + 8],       sr[(k0 + 1) * 129 + m0 + 8],       hi[1], lo[1]);
        split2(sr[(k0 + 8) * 129 + m0],     sr[(k0 + 9) * 129 + m0],           hi[2], lo[2]);
        split2(sr[(k0 + 8) * 129 + m0 + 8], sr[(k0 + 9) * 129 + m0 + 8],       hi[3], lo[3]);
        const int ktg = cg * 2 + ktl;
        const int fi = (ktg * 8 + mt) * 32 + l;
        ob[fi]            = make_uint4(hi[0], hi[1], hi[2], hi[3]);
        ob[fi + A_BLK_F4] = make_uint4(lo[0], lo[1], lo[2], lo[3]);
    }
}

// ============================================================================
// Prep B: weight -> fragment-major hi/lo images. block = (vt 16, cg 8)
// ============================================================================
__global__ void vq_prepB(const float* __restrict__ W) {
    __shared__ float sr2[32 * 257];
    const int vt = blockIdx.x, cg = blockIdx.y, t = threadIdx.x;
    const float* base = W + (size_t)(vt * NTT) * KDIM + cg * 32;

    for (int i = t; i < 256 * 32; i += 256) {
        const int n = i >> 5, c = i & 31;             // coalesced along channels
        sr2[c * 257 + n] = base[(size_t)n * KDIM + c];
    }
    __syncthreads();

    uint4* ob = (uint4*)(g_Bimg + (size_t)vt * 4 * B_VT_F4);
    #pragma unroll
    for (int q = 0; q < 4; q++) {
        const int tup = q * 256 + t;                  // 1024 tuples
        const int ktl = tup >> 9, ntp = (tup >> 5) & 15, l = tup & 31;
        const int nA = ntp * 16 + (l >> 2);
        const int k0 = ktl * 16 + (l & 3) * 2;
        uint32_t hi[4], lo[4];
        split2(sr2[k0 * 257 + nA],           sr2[(k0 + 1) * 257 + nA],     hi[0], lo[0]); // b0 nt0
        split2(sr2[(k0 + 8) * 257 + nA],     sr2[(k0 + 9) * 257 + nA],     hi[1], lo[1]); // b1 nt0
        split2(sr2[k0 * 257 + nA + 8],       sr2[(k0 + 1) * 257 + nA + 8], hi[2], lo[2]); // b0 nt1
        split2(sr2[(k0 + 8) * 257 + nA + 8], sr2[(k0 + 9) * 257 + nA + 8], hi[3], lo[3]); // b1 nt1
        const int ktg = cg * 2 + ktl;
        const int fi = (ktg * 16 + ntp) * 32 + l;
        ob[fi]            = make_uint4(hi[0], hi[1], hi[2], hi[3]);
        ob[fi + B_BLK_F4] = make_uint4(lo[0], lo[1], lo[2], lo[3]);
    }
}

// ---- W transpose for output gather + ||w||^2 (validated in R1) -------------
__global__ void vq_transpose(const float* __restrict__ W) {
    __shared__ float tile[32][33];
    const int v0 = blockIdx.x * 32, c0 = blockIdx.y * 32;
    const int tx = threadIdx.x, ty = threadIdx.y;
    #pragma unroll
    for (int j = 0; j < 32; j += 8)
        tile[ty + j][tx] = W[(size_t)(v0 + ty + j) * KDIM + c0 + tx];
    __syncthreads();
    #pragma unroll
    for (int j = 0; j < 32; j += 8)
        g_Wt[(size_t)(c0 + ty + j) * VCODES + v0 + tx] = tile[tx][ty + j];
}

__global__ void vq_wnorm(const float* __restrict__ W) {
    const int v = blockIdx.x * 8 + (threadIdx.x >> 5);
    const int lane = threadIdx.x & 31;
    const float4* p = reinterpret_cast<const float4*>(W + (size_t)v * KDIM);
    float s = 0.f;
    #pragma unroll
    for (int i = 0; i < 2; i++) {
        float4 x = p[lane * 2 + i];
        s += x.x * x.x + x.y * x.y + x.z * x.z + x.w * x.w;
    }
    #pragma unroll
    for (int o = 16; o > 0; o >>= 1) s += __shfl_xor_sync(0xffffffffu, s, o);
    if (lane == 0) g_wnorm[v] = s;
}

// ============================================================================
// Main: 256 CTAs x 256 threads, 3-stage cp.async pipeline, warp tile 32x128
// ============================================================================
__global__ void __launch_bounds__(256, 1)
vq_main(const float* __restrict__ gf, float* __restrict__ out) {
    extern __shared__ uint4 sm4[];
    const uint32_t smb = smem_u32(sm4);

    const int t  = threadIdx.x;
    const int l  = t & 31;
    const int w  = t >> 5;
    const int wr = w >> 1;       // 0..3  (row group of 32)
    const int wc = w & 1;        // 0..1  (col group of 128)
    const int rt = blockIdx.x;
    const int n0 = rt * MT;
    const int b  = n0 >> 12;
    const int p0 = n0 & (SPATIAL - 1);

    const uint4* Abase = (const uint4*)(g_Aimg + (size_t)rt * A_RT_U32);
    const uint4* Bbase = (const uint4*)g_Bimg;

    // ---- producer lambda: stage a 32-k chunk --------------------------------
    auto issue = [&](int ch, int slot) {
        const int vt = ch >> 5, cc = ch & 31;
        const int pass = cc >> 3, kc = cc & 7;
        const uint4* As = Abase + (pass >> 1) * A_BLK_F4 + kc * A_CH_F4;
        const uint4* Bs = Bbase + (size_t)vt * B_VT_F4 + (pass & 1) * B_BLK_F4 + kc * B_CH_F4;
        const uint32_t sb = smb + slot * STAGE_F4 * 16;
        cp16(sb + t * 16,            As + t);
        cp16(sb + (t + 256) * 16,    As + t + 256);
        const uint32_t bb = sb + A_CH_F4 * 16;
        #pragma unroll
        for (int q = 0; q < 4; q++)
            cp16(bb + (t + 256 * q) * 16, Bs + t + 256 * q);
        CP_COMMIT();
    };

    float acc[2][16][4];
    float rmin[4];
    int   ridx[4];
    #pragma unroll
    for (int q = 0; q < 4; q++) { rmin[q] = 3.4e38f; ridx[q] = 0; }

    issue(0, 0);
    issue(1, 1);

    for (int ch = 0; ch < TOTAL_CH; ch++) {
        CP_WAIT(1);
        __syncthreads();
        if (ch + 2 < TOTAL_CH) issue(ch + 2, (ch + 2) % NSTAGES);

        const uint4* S = sm4 + (ch % NSTAGES) * STAGE_F4;
        const int cc = ch & 31;

        if (cc == 0) {
            #pragma unroll
            for (int i = 0; i < 2; i++)
                #pragma unroll
                for (int j = 0; j < 16; j++)
                    #pragma unroll
                    for (int e = 0; e < 4; e++) acc[i][j][e] = 0.f;
        }

        #pragma unroll
        for (int ktl = 0; ktl < 2; ktl++) {
            const uint4 a0 = S[(ktl * 8 + wr * 2 + 0) * 32 + l];
            const uint4 a1 = S[(ktl * 8 + wr * 2 + 1) * 32 + l];
            #pragma unroll
            for (int jp = 0; jp < 8; jp++) {
                const uint4 bb = S[A_CH_F4 + (ktl * 16 + wc * 8 + jp) * 32 + l];
                mma16816(acc[0][2 * jp],     a0, bb.x, bb.y);
                mma16816(acc[1][2 * jp],     a1, bb.x, bb.y);
                mma16816(acc[0][2 * jp + 1], a0, bb.z, bb.w);
                mma16816(acc[1][2 * jp + 1], a1, bb.z, bb.w);
            }
        }

        if (cc == 31) {
            // epilogue: d = ||w||^2 - 2*score ; lex (d, idx) min = jnp.argmin
            const int vt = ch >> 5;
            #pragma unroll
            for (int i = 0; i < 2; i++) {
                #pragma unroll
                for (int jn = 0; jn < 16; jn++) {
                    const int cb = vt * NTT + (wc * 8 + (jn >> 1)) * 16
                                 + (jn & 1) * 8 + 2 * (l & 3);
                    const float w0 = __ldg(&g_wnorm[cb]);
                    const float w1 = __ldg(&g_wnorm[cb + 1]);
                    const float d0 = fmaf(-2.f, acc[i][jn][0], w0);
                    const float d1 = fmaf(-2.f, acc[i][jn][1], w1);
                    const float d2 = fmaf(-2.f, acc[i][jn][2], w0);
                    const float d3 = fmaf(-2.f, acc[i][jn][3], w1);
                    const int q0 = i * 2, q1 = i * 2 + 1;
                    if (d0 < rmin[q0] || (d0 == rmin[q0] && cb     < ridx[q0])) { rmin[q0] = d0; ridx[q0] = cb; }
                    if (d1 < rmin[q0] || (d1 == rmin[q0] && cb + 1 < ridx[q0])) { rmin[q0] = d1; ridx[q0] = cb + 1; }
                    if (d2 < rmin[q1] || (d2 == rmin[q1] && cb     < ridx[q1])) { rmin[q1] = d2; ridx[q1] = cb; }
                    if (d3 < rmin[q1] || (d3 == rmin[q1] && cb + 1 < ridx[q1])) { rmin[q1] = d3; ridx[q1] = cb + 1; }
                }
            }
        }
    }
    CP_WAIT(0);
    __syncthreads();

    // ---- cross-warp argmin merge (smem aliases pipeline stages) ------------
    float* dmin_s   = (float*)sm4;             // [128][8]
    int*   idx_s    = (int*)(dmin_s + 1024);   // [128][8]
    int*   rowidx_s = idx_s + 1024;            // [128]
    float* red      = (float*)(rowidx_s + 128);// [256]

    const int slot = wc * 4 + (l & 3);
    #pragma unroll
    for (int q = 0; q < 4; q++) {
        const int row = wr * 32 + (q >> 1) * 16 + (q & 1) * 8 + (l >> 2);
        dmin_s[row * 8 + slot] = rmin[q];
        idx_s[row * 8 + slot]  = ridx[q];
    }
    __syncthreads();
    if (t < MT) {
        float bd = dmin_s[t * 8];
        int   bi = idx_s[t * 8];
        #pragma unroll
        for (int s = 1; s < 8; s++) {
            const float d = dmin_s[t * 8 + s];
            const int   v = idx_s[t * 8 + s];
            if (d < bd || (d == bd && v < bi)) { bd = d; bi = v; }
        }
        rowidx_s[t] = bi;
        out[2 * NQ + n0 + t] = (float)bi;      // enc_idx
    }
    __syncthreads();

    // ---- output phase: gather + straight-through + MSE partial -------------
    float diffsum = 0.f;
    const size_t obase = (size_t)b * KDIM * SPATIAL + p0;
    for (int i = t; i < MT * KDIM; i += 256) {
        const int c = i >> 7, r = i & 127;
        const int vi = rowidx_s[r];
        const float qv = g_Wt[(size_t)c * VCODES + vi];
        const float gv = gf[obase + (size_t)c * SPATIAL + r];
        const float st = (qv - gv) + gv;
        const float dd = gv - qv;
        diffsum += dd * dd;
        const size_t o = obase + (size_t)c * SPATIAL + r;
        out[o]      = qv;
        out[NQ + o] = st;
    }

    red[t] = diffsum;
    __syncthreads();
    #pragma unroll
    for (int o = 128; o > 0; o >>= 1) {
        if (t < o) red[t] += red[t + o];
        __syncthreads();
    }
    if (t == 0) g_partial[rt] = red[0];
}

__global__ void vq_final(float* __restrict__ out) {
    __shared__ float red[NRT];
    const int t = threadIdx.x;
    red[t] = g_partial[t];
    __syncthreads();
    #pragma unroll
    for (int o = 128; o > 0; o >>= 1) {
        if (t < o) red[t] += red[t + o];
        __syncthreads();
    }
    if (t == 0) out[2 * NQ + NROWS] = red[0] * (1.f / (float)NQ);
}

// ============================================================================
extern "C" void kernel_launch(void* const* d_in, const int* in_sizes, int n_in,
                              void* d_out, int out_size) {
    const float* grid_feat = (const float*)d_in[0];
    const float* weight    = (const float*)d_in[1];
    float* out = (float*)d_out;

    cudaFuncSetAttribute(vq_main,
                         cudaFuncAttributeMaxDynamicSharedMemorySize, SMEM_MAIN);

    vq_prepA<<<dim3(NRT, 8), 256>>>(grid_feat);
    vq_prepB<<<dim3(NVT, 8), 256>>>(weight);
    vq_transpose<<<dim3(VCODES / 32, KDIM / 32), dim3(32, 8)>>>(weight);
    vq_wnorm<<<VCODES / 8, 256>>>(weight);
    vq_main<<<NRT, 256, SMEM_MAIN>>>(grid_feat, out);
    vq_final<<<1, NRT>>>(out);
}

// round 5
// speedup vs baseline: 1.6873x; 1.1767x over previous
#include <cuda_runtime.h>
#include <cuda_fp16.h>
#include <cstdint>
#include <cstddef>

// ============================================================================
// VQ quantizer: legacy mma.sync m16n8k16 fp16, 3-pass hi/lo split
// + per-row margin check with exact-fp32 fallback (provably safe argmin)
//   grid_feat [8,256,16,16,16] f32 ; weight [4096,256] f32
// out: quant_feat[8.4M] | quant_feat_st[8.4M] | enc_idx[32768] | quant_diff[1]
// ============================================================================

namespace {
constexpr int KDIM    = 256;
constexpr int VCODES  = 4096;
constexpr int SPATIAL = 4096;
constexpr int NROWS   = 32768;
constexpr long long NQ = 8388608LL;

constexpr int MT  = 128;            // rows per CTA
constexpr int NTT = 256;            // codes per v-tile
constexpr int NRT = NROWS / MT;     // 256 row-tile CTAs
constexpr int NVT = VCODES / NTT;   // 16 v-tiles

constexpr int A_RT_U32  = 32768;    // A image per rt (hi+lo), u32
constexpr int A_BLK_F4  = 4096;
constexpr int A_KT_F4   = 256;
constexpr int B_VT_F4   = 16384;    // B image per vt (hi+lo), f4
constexpr int B_BLK_F4  = 8192;
constexpr int B_KT_F4   = 512;

// 3 passes: hi*hi, hi*lo, lo*hi ; chunk = 32 k = 2 kt
constexpr int CH_PER_VT = 24;
constexpr int TOTAL_CH  = NVT * CH_PER_VT;      // 384
constexpr int A_CH_F4   = 2 * A_KT_F4;          // 512 f4 (8KB)
constexpr int B_CH_F4   = 2 * B_KT_F4;          // 1024 f4 (16KB)
constexpr int STAGE_F4  = A_CH_F4 + B_CH_F4;    // 1536 f4 (24KB)
constexpr int NSTAGES   = 4;
constexpr int SMEM_MAIN = NSTAGES * STAGE_F4 * 16;   // 98304 B

constexpr float MARGIN = 1e-3f;     // ~10-15 sigma of 3-pass distance error
}

// --------------------------- device scratch --------------------------------
__device__ uint32_t g_Aimg[(size_t)NRT * A_RT_U32];   // 32 MB
__device__ uint32_t g_Bimg[(size_t)NVT * 4 * B_VT_F4];// 4 MB
__device__ float    g_Wt[KDIM * VCODES];              // W^T for gather
__device__ float    g_wnorm[VCODES];
__device__ float    g_partial[NRT];
__device__ int      g_nflag;
__device__ int      g_flagrows[4096];

// --------------------------- helpers ---------------------------------------
__device__ __forceinline__ uint32_t smem_u32(const void* p) {
    uint32_t a;
    asm("{ .reg .u64 t; cvta.to.shared.u64 t, %1; cvt.u32.u64 %0, t; }"
        : "=r"(a) : "l"(p));
    return a;
}
__device__ __forceinline__ void cp16(uint32_t s, const void* g) {
    asm volatile("cp.async.cg.shared.global [%0], [%1], 16;" :: "r"(s), "l"(g));
}
#define CP_COMMIT()  asm volatile("cp.async.commit_group;" ::: "memory")
#define CP_WAIT(N)   asm volatile("cp.async.wait_group %0;" :: "n"(N) : "memory")

__device__ __forceinline__ void mma16816(float* c, const uint4& a,
                                         uint32_t b0, uint32_t b1) {
    asm volatile(
        "mma.sync.aligned.m16n8k16.row.col.f32.f16.f16.f32 "
        "{%0,%1,%2,%3}, {%4,%5,%6,%7}, {%8,%9}, {%0,%1,%2,%3};"
        : "+f"(c[0]), "+f"(c[1]), "+f"(c[2]), "+f"(c[3])
        : "r"(a.x), "r"(a.y), "r"(a.z), "r"(a.w), "r"(b0), "r"(b1));
}

__device__ __forceinline__ void split2(float v0, float v1,
                                       uint32_t& hi, uint32_t& lo) {
    __half h0 = __float2half_rn(v0), h1 = __float2half_rn(v1);
    __half l0 = __float2half_rn(v0 - __half2float(h0));
    __half l1 = __float2half_rn(v1 - __half2float(h1));
    hi = (uint32_t)__half_as_ushort(h0) | ((uint32_t)__half_as_ushort(h1) << 16);
    lo = (uint32_t)__half_as_ushort(l0) | ((uint32_t)__half_as_ushort(l1) << 16);
}

// ============================================================================
// Prep A: grid_feat -> fragment-major hi/lo fp16 images (validated R3)
// ============================================================================
__global__ void vq_prepA(const float* __restrict__ gf) {
    __shared__ float sr[32 * 129];
    const int rt = blockIdx.x, cg = blockIdx.y, t = threadIdx.x;
    const int n0 = rt * MT, b = n0 >> 12, p0 = n0 & (SPATIAL - 1);
    const float* base = gf + (size_t)b * KDIM * SPATIAL + (size_t)(cg * 32) * SPATIAL + p0;

    for (int i = t; i < 32 * 128; i += 256) {
        const int c = i >> 7, r = i & 127;
        sr[c * 129 + r] = base[(size_t)c * SPATIAL + r];
    }
    __syncthreads();

    uint4* ob = (uint4*)(g_Aimg + (size_t)rt * A_RT_U32);
    #pragma unroll
    for (int q = 0; q < 2; q++) {
        const int tup = q * 256 + t;
        const int ktl = tup >> 8, mt = (tup >> 5) & 7, l = tup & 31;
        const int m0 = mt * 16 + (l >> 2);
        const int k0 = ktl * 16 + (l & 3) * 2;
        uint32_t hi[4], lo[4];
        split2(sr[k0 * 129 + m0],           sr[(k0 + 1) * 129 + m0],           hi[0], lo[0]);
        split2(sr[k0 * 129 + m0 + 8],       sr[(k0 + 1) * 129 + m0 + 8],       hi[1], lo[1]);
        split2(sr[(k0 + 8) * 129 + m0],     sr[(k0 + 9) * 129 + m0],           hi[2], lo[2]);
        split2(sr[(k0 + 8) * 129 + m0 + 8], sr[(k0 + 9) * 129 + m0 + 8],       hi[3], lo[3]);
        const int ktg = cg * 2 + ktl;
        const int fi = (ktg * 8 + mt) * 32 + l;
        ob[fi]            = make_uint4(hi[0], hi[1], hi[2], hi[3]);
        ob[fi + A_BLK_F4] = make_uint4(lo[0], lo[1], lo[2], lo[3]);
    }
}

// ============================================================================
// Prep B: weight -> fragment-major hi/lo images (validated R3)
// ============================================================================
__global__ void vq_prepB(const float* __restrict__ W) {
    __shared__ float sr2[32 * 257];
    const int vt = blockIdx.x, cg = blockIdx.y, t = threadIdx.x;
    const float* base = W + (size_t)(vt * NTT) * KDIM + cg * 32;

    for (int i = t; i < 256 * 32; i += 256) {
        const int n = i >> 5, c = i & 31;
        sr2[c * 257 + n] = base[(size_t)n * KDIM + c];
    }
    __syncthreads();

    uint4* ob = (uint4*)(g_Bimg + (size_t)vt * 4 * B_VT_F4);
    #pragma unroll
    for (int q = 0; q < 4; q++) {
        const int tup = q * 256 + t;
        const int ktl = tup >> 9, ntp = (tup >> 5) & 15, l = tup & 31;
        const int nA = ntp * 16 + (l >> 2);
        const int k0 = ktl * 16 + (l & 3) * 2;
        uint32_t hi[4], lo[4];
        split2(sr2[k0 * 257 + nA],           sr2[(k0 + 1) * 257 + nA],     hi[0], lo[0]);
        split2(sr2[(k0 + 8) * 257 + nA],     sr2[(k0 + 9) * 257 + nA],     hi[1], lo[1]);
        split2(sr2[k0 * 257 + nA + 8],       sr2[(k0 + 1) * 257 + nA + 8], hi[2], lo[2]);
        split2(sr2[(k0 + 8) * 257 + nA + 8], sr2[(k0 + 9) * 257 + nA + 8], hi[3], lo[3]);
        const int ktg = cg * 2 + ktl;
        const int fi = (ktg * 16 + ntp) * 32 + l;
        ob[fi]            = make_uint4(hi[0], hi[1], hi[2], hi[3]);
        ob[fi + B_BLK_F4] = make_uint4(lo[0], lo[1], lo[2], lo[3]);
    }
}

// ---- W transpose + ||w||^2 (validated R1) ; also resets flag counter -------
__global__ void vq_transpose(const float* __restrict__ W) {
    __shared__ float tile[32][33];
    const int v0 = blockIdx.x * 32, c0 = blockIdx.y * 32;
    const int tx = threadIdx.x, ty = threadIdx.y;
    #pragma unroll
    for (int j = 0; j < 32; j += 8)
        tile[ty + j][tx] = W[(size_t)(v0 + ty + j) * KDIM + c0 + tx];
    __syncthreads();
    #pragma unroll
    for (int j = 0; j < 32; j += 8)
        g_Wt[(size_t)(c0 + ty + j) * VCODES + v0 + tx] = tile[tx][ty + j];
}

__global__ void vq_wnorm(const float* __restrict__ W) {
    if (blockIdx.x == 0 && threadIdx.x == 0) g_nflag = 0;
    const int v = blockIdx.x * 8 + (threadIdx.x >> 5);
    const int lane = threadIdx.x & 31;
    const float4* p = reinterpret_cast<const float4*>(W + (size_t)v * KDIM);
    float s = 0.f;
    #pragma unroll
    for (int i = 0; i < 2; i++) {
        float4 x = p[lane * 2 + i];
        s += x.x * x.x + x.y * x.y + x.z * x.z + x.w * x.w;
    }
    #pragma unroll
    for (int o = 16; o > 0; o >>= 1) s += __shfl_xor_sync(0xffffffffu, s, o);
    if (lane == 0) g_wnorm[v] = s;
}

// ============================================================================
// Main: 256 CTAs x 256 threads, 4-stage cp.async pipeline, warp tile 32x128
// ============================================================================
__global__ void __launch_bounds__(256, 1)
vq_main(const float* __restrict__ gf, float* __restrict__ out) {
    extern __shared__ uint4 sm4[];
    const uint32_t smb = smem_u32(sm4);

    const int t  = threadIdx.x;
    const int l  = t & 31;
    const int w  = t >> 5;
    const int wr = w >> 1;       // 0..3
    const int wc = w & 1;        // 0..1
    const int rt = blockIdx.x;
    const int n0 = rt * MT;
    const int b  = n0 >> 12;
    const int p0 = n0 & (SPATIAL - 1);

    const uint4* Abase = (const uint4*)(g_Aimg + (size_t)rt * A_RT_U32);
    const uint4* Bbase = (const uint4*)g_Bimg;

    // pass 0: Ahi*Bhi ; pass 1: Ahi*Blo ; pass 2: Alo*Bhi
    auto issue = [&](int ch, int slot) {
        const int vt = ch / CH_PER_VT, cc = ch - vt * CH_PER_VT;
        const int pass = cc >> 3, kc = cc & 7;
        const uint4* As = Abase + (pass == 2 ? A_BLK_F4 : 0) + kc * A_CH_F4;
        const uint4* Bs = Bbase + (size_t)vt * B_VT_F4
                        + (pass == 1 ? B_BLK_F4 : 0) + kc * B_CH_F4;
        const uint32_t sb = smb + slot * STAGE_F4 * 16;
        cp16(sb + t * 16,            As + t);
        cp16(sb + (t + 256) * 16,    As + t + 256);
        const uint32_t bb = sb + A_CH_F4 * 16;
        #pragma unroll
        for (int q = 0; q < 4; q++)
            cp16(bb + (t + 256 * q) * 16, Bs + t + 256 * q);
        CP_COMMIT();
    };

    float acc[2][16][4];
    float rmin[4], rmin2[4];
    int   ridx[4];
    #pragma unroll
    for (int q = 0; q < 4; q++) { rmin[q] = 3.4e38f; rmin2[q] = 3.4e38f; ridx[q] = 0; }

    issue(0, 0); issue(1, 1); issue(2, 2);

    for (int ch = 0; ch < TOTAL_CH; ch++) {
        if (ch + 3 < TOTAL_CH) {
            CP_WAIT(2);                 // groups <= ch complete
            __syncthreads();            // all warps done reading slot (ch+3)%4
            issue(ch + 3, (ch + 3) & 3);
        } else {
            CP_WAIT(0);                 // tail: everything complete (fixes R3 race)
            __syncthreads();
        }

        const uint4* S = sm4 + (ch & 3) * STAGE_F4;
        const int vt = ch / CH_PER_VT, cc = ch - vt * CH_PER_VT;

        if (cc == 0) {
            #pragma unroll
            for (int i = 0; i < 2; i++)
                #pragma unroll
                for (int j = 0; j < 16; j++)
                    #pragma unroll
                    for (int e = 0; e < 4; e++) acc[i][j][e] = 0.f;
        }

        #pragma unroll
        for (int ktl = 0; ktl < 2; ktl++) {
            const uint4 a0 = S[(ktl * 8 + wr * 2 + 0) * 32 + l];
            const uint4 a1 = S[(ktl * 8 + wr * 2 + 1) * 32 + l];
            #pragma unroll
            for (int jp = 0; jp < 8; jp++) {
                const uint4 bb = S[A_CH_F4 + (ktl * 16 + wc * 8 + jp) * 32 + l];
                mma16816(acc[0][2 * jp],     a0, bb.x, bb.y);
                mma16816(acc[1][2 * jp],     a1, bb.x, bb.y);
                mma16816(acc[0][2 * jp + 1], a0, bb.z, bb.w);
                mma16816(acc[1][2 * jp + 1], a1, bb.z, bb.w);
            }
        }

        if (cc == CH_PER_VT - 1) {
            // epilogue: d = ||w||^2 - 2*score ; track (min1, idx1) lex + min2
            #pragma unroll
            for (int i = 0; i < 2; i++) {
                #pragma unroll
                for (int jn = 0; jn < 16; jn++) {
                    const int cb = vt * NTT + (wc * 8 + (jn >> 1)) * 16
                                 + (jn & 1) * 8 + 2 * (l & 3);
                    const float w0 = __ldg(&g_wnorm[cb]);
                    const float w1 = __ldg(&g_wnorm[cb + 1]);
                    const float d0 = fmaf(-2.f, acc[i][jn][0], w0);
                    const float d1 = fmaf(-2.f, acc[i][jn][1], w1);
                    const float d2 = fmaf(-2.f, acc[i][jn][2], w0);
                    const float d3 = fmaf(-2.f, acc[i][jn][3], w1);
                    const int q0 = i * 2, q1 = i * 2 + 1;
                    if (d0 < rmin[q0]) { rmin2[q0] = rmin[q0]; rmin[q0] = d0; ridx[q0] = cb; }
                    else if (d0 < rmin2[q0]) rmin2[q0] = d0;
                    if (d1 < rmin[q0]) { rmin2[q0] = rmin[q0]; rmin[q0] = d1; ridx[q0] = cb + 1; }
                    else if (d1 < rmin2[q0]) rmin2[q0] = d1;
                    if (d2 < rmin[q1]) { rmin2[q1] = rmin[q1]; rmin[q1] = d2; ridx[q1] = cb; }
                    else if (d2 < rmin2[q1]) rmin2[q1] = d2;
                    if (d3 < rmin[q1]) { rmin2[q1] = rmin[q1]; rmin[q1] = d3; ridx[q1] = cb + 1; }
                    else if (d3 < rmin2[q1]) rmin2[q1] = d3;
                }
            }
        }
    }
    CP_WAIT(0);
    __syncthreads();

    // ---- cross-warp argmin merge (smem aliases pipeline stages) ------------
    float* dmin_s   = (float*)sm4;              // [128][8]
    int*   idx_s    = (int*)(dmin_s + 1024);    // [128][8]
    float* dmin2_s  = (float*)(idx_s + 1024);   // [128][8]
    int*   rowidx_s = (int*)(dmin2_s + 1024);   // [128]
    float* red      = (float*)(rowidx_s + 128); // [256]

    const int slot = wc * 4 + (l & 3);
    #pragma unroll
    for (int q = 0; q < 4; q++) {
        const int row = wr * 32 + (q >> 1) * 16 + (q & 1) * 8 + (l >> 2);
        dmin_s[row * 8 + slot]  = rmin[q];
        idx_s[row * 8 + slot]   = ridx[q];
        dmin2_s[row * 8 + slot] = rmin2[q];
    }
    __syncthreads();
    if (t < MT) {
        float bd = 3.4e38f, bd2 = 3.4e38f;
        int   bi = 0;
        #pragma unroll
        for (int s = 0; s < 8; s++) {
            const float d = dmin_s[t * 8 + s];
            const int   v = idx_s[t * 8 + s];
            if (d < bd || (d == bd && v < bi)) { bd2 = fminf(bd2, bd); bd = d; bi = v; }
            else bd2 = fminf(bd2, d);
            bd2 = fminf(bd2, dmin2_s[t * 8 + s]);
        }
        rowidx_s[t] = bi;
        out[2 * NQ + n0 + t] = (float)bi;       // enc_idx
        if (bd2 - bd < MARGIN) {                // ambiguous -> exact fallback
            const int pos = atomicAdd(&g_nflag, 1);
            if (pos < 4096) g_flagrows[pos] = n0 + t;
        }
    }
    __syncthreads();

    // ---- output phase: gather + straight-through + MSE partial -------------
    float diffsum = 0.f;
    const size_t obase = (size_t)b * KDIM * SPATIAL + p0;
    for (int i = t; i < MT * KDIM; i += 256) {
        const int c = i >> 7, r = i & 127;
        const int vi = rowidx_s[r];
        const float qv = g_Wt[(size_t)c * VCODES + vi];
        const float gv = gf[obase + (size_t)c * SPATIAL + r];
        const float st = (qv - gv) + gv;
        const float dd = gv - qv;
        diffsum += dd * dd;
        const size_t o = obase + (size_t)c * SPATIAL + r;
        out[o]      = qv;
        out[NQ + o] = st;
    }

    red[t] = diffsum;
    __syncthreads();
    #pragma unroll
    for (int o = 128; o > 0; o >>= 1) {
        if (t < o) red[t] += red[t + o];
        __syncthreads();
    }
    if (t == 0) g_partial[rt] = red[0];
}

// ============================================================================
// Exact fp32 fallback for flagged (ambiguous-margin) rows
// ============================================================================
__global__ void vq_fix(const float* __restrict__ gf, const float* __restrict__ W,
                       float* __restrict__ out) {
    const int nf = min(g_nflag, 4096);
    __shared__ float fsh[KDIM];
    __shared__ float dsh[256];
    __shared__ int   ish[256];
    const int t = threadIdx.x;

    for (int fi = blockIdx.x; fi < nf; fi += gridDim.x) {
        const int row = g_flagrows[fi];
        const int b = row >> 12, p = row & (SPATIAL - 1);
        fsh[t] = gf[(size_t)b * KDIM * SPATIAL + (size_t)t * SPATIAL + p];
        __syncthreads();

        float bd = 3.4e38f; int bi = 0;
        for (int v = t; v < VCODES; v += 256) {
            const float* wr = W + (size_t)v * KDIM;
            float dot = 0.f;
            #pragma unroll 8
            for (int c = 0; c < KDIM; c++) dot = fmaf(fsh[c], wr[c], dot);
            const float d = g_wnorm[v] - 2.f * dot;
            if (d < bd) { bd = d; bi = v; }          // ascending v per thread
        }
        dsh[t] = bd; ish[t] = bi;
        __syncthreads();
        #pragma unroll
        for (int o = 128; o > 0; o >>= 1) {
            if (t < o) {
                const float d2 = dsh[t + o]; const int i2 = ish[t + o];
                if (d2 < dsh[t] || (d2 == dsh[t] && i2 < ish[t])) { dsh[t] = d2; ish[t] = i2; }
            }
            __syncthreads();
        }
        const int newi = ish[0];
        const int oldi = (int)out[2 * NQ + row];
        __syncthreads();

        if (newi != oldi) {
            const float gv = fsh[t];
            const float qn = W[(size_t)newi * KDIM + t];
            const float qo = W[(size_t)oldi * KDIM + t];
            const size_t o = (size_t)b * KDIM * SPATIAL + (size_t)t * SPATIAL + p;
            out[o]      = qn;
            out[NQ + o] = (qn - gv) + gv;
            dsh[t] = (gv - qn) * (gv - qn) - (gv - qo) * (gv - qo);
            __syncthreads();
            #pragma unroll
            for (int o2 = 128; o2 > 0; o2 >>= 1) {
                if (t < o2) dsh[t] += dsh[t + o2];
                __syncthreads();
            }
            if (t == 0) {
                atomicAdd(&g_partial[row / MT], dsh[0]);
                out[2 * NQ + row] = (float)newi;
            }
        }
        __syncthreads();
    }
}

__global__ void vq_final(float* __restrict__ out) {
    __shared__ float red[NRT];
    const int t = threadIdx.x;
    red[t] = g_partial[t];
    __syncthreads();
    #pragma unroll
    for (int o = 128; o > 0; o >>= 1) {
        if (t < o) red[t] += red[t + o];
        __syncthreads();
    }
    if (t == 0) out[2 * NQ + NROWS] = red[0] * (1.f / (float)NQ);
}

// ============================================================================
extern "C" void kernel_launch(void* const* d_in, const int* in_sizes, int n_in,
                              void* d_out, int out_size) {
    const float* grid_feat = (const float*)d_in[0];
    const float* weight    = (const float*)d_in[1];
    float* out = (float*)d_out;

    cudaFuncSetAttribute(vq_main,
                         cudaFuncAttributeMaxDynamicSharedMemorySize, SMEM_MAIN);

    vq_prepA<<<dim3(NRT, 8), 256>>>(grid_feat);
    vq_prepB<<<dim3(NVT, 8), 256>>>(weight);
    vq_transpose<<<dim3(VCODES / 32, KDIM / 32), dim3(32, 8)>>>(weight);
    vq_wnorm<<<VCODES / 8, 256>>>(weight);
    vq_main<<<NRT, 256, SMEM_MAIN>>>(grid_feat, out);
    vq_fix<<<64, 256>>>(grid_feat, weight, out);
    vq_final<<<1, NRT>>>(out);
}